// round 4
// baseline (speedup 1.0000x reference)
#include <cuda_runtime.h>
#include <math.h>

// Problem constants
#define Bsz   4096
#define Nn    32
#define Hh    8
#define Dd    64
#define HIDd  512
#define MROWS (Bsz * Nn)                 // 131072
#define QKV_COLS (3 * HIDd)              // 1536

static const size_t OUT_ELEMS  = (size_t)MROWS * HIDd;        // 67108864
static const size_t ATTN_ELEMS = (size_t)Bsz * Hh * Nn * Nn;  // 33554432

// Scratch (no allocations allowed anywhere)
__device__ float g_qkv[(size_t)MROWS * QKV_COLS];   // ~805 MB
__device__ float g_ctx[(size_t)MROWS * HIDd];       // ~268 MB
__device__ float g_attn_fb[(size_t)Bsz * Hh * Nn * Nn];
__device__ unsigned int g_mask_bits[32];

// ---------------------------------------------------------------------------
// Mask decode: sparse_mask is bool [32,32]; storage width is ambiguous
// (1-byte bool vs 4-byte int32/float32). Diagonal is always true, so under
// 1-byte storage raw[33*i] != 0 for all i; under 4-byte 0/1 storage at least
// one of those bytes is 0. Build per-row bitmasks.
// ---------------------------------------------------------------------------
__global__ void decode_mask_kernel(const unsigned char* __restrict__ raw) {
    __shared__ int onebyte;
    if (threadIdx.x == 0) {
        int ok = 1;
        for (int i = 0; i < 32; ++i) if (raw[33 * i] == 0) ok = 0;
        onebyte = ok;
    }
    __syncthreads();
    int i = threadIdx.x;  // row
    unsigned int bits = 0;
    if (onebyte) {
        for (int j = 0; j < 32; ++j)
            if (raw[i * 32 + j] != 0) bits |= (1u << j);
    } else {
        const unsigned int* w = (const unsigned int*)raw;
        for (int j = 0; j < 32; ++j)
            if (w[i * 32 + j] != 0) bits |= (1u << j);
    }
    g_mask_bits[i] = bits;
}

// ---------------------------------------------------------------------------
// SGEMM (NT): C[m,n] = sum_k A[m,k]*B[n,k] + bias[n]
// A: [M,K] row-major, B: [N,K] row-major, C: [M,N] row-major.
// BM=BN=128, BK=16, 256 threads, 8x8 register tiles. M,N,K are multiples of
// the tile sizes here, so no bounds checks.
// ---------------------------------------------------------------------------
#define GBM 128
#define GBN 128
#define GBK 16
#define GTM 8
#define GTN 8

__global__ void __launch_bounds__(256)
sgemm_nt_bias(const float* __restrict__ A, const float* __restrict__ B,
              const float* __restrict__ bias, float* __restrict__ C,
              int M, int N, int K)
{
    __shared__ float As[GBK][GBM + 4];
    __shared__ float Bs[GBK][GBN + 4];

    const int bm = blockIdx.x * GBM;
    const int bn = blockIdx.y * GBN;
    const int t  = threadIdx.x;

    const int tx = t & 15;        // 0..15  (N direction)
    const int ty = t >> 4;        // 0..15  (M direction)
    const int row0 = ty * GTM;
    const int col0 = tx * GTN;

    float acc[GTM][GTN];
#pragma unroll
    for (int i = 0; i < GTM; ++i)
#pragma unroll
        for (int j = 0; j < GTN; ++j) acc[i][j] = 0.0f;

    for (int k0 = 0; k0 < K; k0 += GBK) {
        // Load 128x16 tiles of A and B (512 float4 each, 2 per thread),
        // stored transposed: [k][row].
#pragma unroll
        for (int r = 0; r < 2; ++r) {
            int idx = t + 256 * r;          // 0..511
            int row = idx >> 2;             // 0..127
            int kq  = (idx & 3) * 4;        // 0,4,8,12
            float4 a4 = *(const float4*)&A[(size_t)(bm + row) * K + k0 + kq];
            As[kq + 0][row] = a4.x;
            As[kq + 1][row] = a4.y;
            As[kq + 2][row] = a4.z;
            As[kq + 3][row] = a4.w;
            float4 b4 = *(const float4*)&B[(size_t)(bn + row) * K + k0 + kq];
            Bs[kq + 0][row] = b4.x;
            Bs[kq + 1][row] = b4.y;
            Bs[kq + 2][row] = b4.z;
            Bs[kq + 3][row] = b4.w;
        }
        __syncthreads();

#pragma unroll
        for (int kk = 0; kk < GBK; ++kk) {
            float a[GTM], b[GTN];
            *(float4*)&a[0] = *(const float4*)&As[kk][row0];
            *(float4*)&a[4] = *(const float4*)&As[kk][row0 + 4];
            *(float4*)&b[0] = *(const float4*)&Bs[kk][col0];
            *(float4*)&b[4] = *(const float4*)&Bs[kk][col0 + 4];
#pragma unroll
            for (int i = 0; i < GTM; ++i)
#pragma unroll
                for (int j = 0; j < GTN; ++j)
                    acc[i][j] += a[i] * b[j];
        }
        __syncthreads();
    }

    float bb[GTN];
#pragma unroll
    for (int j = 0; j < GTN; ++j) bb[j] = bias[bn + col0 + j];

#pragma unroll
    for (int i = 0; i < GTM; ++i) {
        size_t off = (size_t)(bm + row0 + i) * N + bn + col0;
        float4 o0, o1;
        o0.x = acc[i][0] + bb[0]; o0.y = acc[i][1] + bb[1];
        o0.z = acc[i][2] + bb[2]; o0.w = acc[i][3] + bb[3];
        o1.x = acc[i][4] + bb[4]; o1.y = acc[i][5] + bb[5];
        o1.z = acc[i][6] + bb[6]; o1.w = acc[i][7] + bb[7];
        *(float4*)&C[off]     = o0;
        *(float4*)&C[off + 4] = o1;
    }
}

// ---------------------------------------------------------------------------
// Attention: one block per (b,h). Q,K,V are 32x64 slices of g_qkv.
// scores = QK^T/8, mask (-1e9), softmax, attn out, ctx = P @ V.
// ---------------------------------------------------------------------------
__global__ void __launch_bounds__(128)
attn_kernel(const float* __restrict__ qkv, float* __restrict__ ctx,
            float* __restrict__ attn_out)
{
    __shared__ float Qs[32][64];
    __shared__ float Ks[32][65];   // pad -> conflict-free K[j][d] with j varying
    __shared__ float Vs[32][64];
    __shared__ float Ss[32][33];   // pad -> conflict-free row access

    const int bh = blockIdx.x;           // b*H + h
    const int b  = bh >> 3;
    const int h  = bh & 7;
    const int t  = threadIdx.x;

    const float* base = qkv + (size_t)b * Nn * QKV_COLS + h * Dd;

    // Load Q/K/V (512 float4 each matrix; 4 per thread per matrix)
#pragma unroll
    for (int r = 0; r < 4; ++r) {
        int idx = t + 128 * r;           // 0..511
        int i   = idx >> 4;              // row 0..31
        int d4  = (idx & 15) * 4;        // 0..60
        size_t ro = (size_t)i * QKV_COLS + d4;
        float4 q = *(const float4*)&base[ro];
        float4 k = *(const float4*)&base[ro + HIDd];
        float4 v = *(const float4*)&base[ro + 2 * HIDd];
        *(float4*)&Qs[i][d4] = q;
        Ks[i][d4 + 0] = k.x; Ks[i][d4 + 1] = k.y;
        Ks[i][d4 + 2] = k.z; Ks[i][d4 + 3] = k.w;
        *(float4*)&Vs[i][d4] = v;
    }
    __syncthreads();

    // Scores + mask. Lane-contiguous j => Qs broadcast, Ks conflict-free.
#pragma unroll
    for (int r = 0; r < 8; ++r) {
        int p = t + 128 * r;             // 0..1023
        int i = p >> 5, j = p & 31;
        float s = 0.0f;
#pragma unroll
        for (int d = 0; d < 64; ++d) s += Qs[i][d] * Ks[j][d];
        bool m = (g_mask_bits[i] >> j) & 1u;
        Ss[i][j] = m ? s * 0.125f : -1e9f;
    }
    __syncthreads();

    // Softmax: one thread per row (exact expf for fp32 parity)
    if (t < 32) {
        float mx = -1e30f;
#pragma unroll
        for (int j = 0; j < 32; ++j) mx = fmaxf(mx, Ss[t][j]);
        float sum = 0.0f;
#pragma unroll
        for (int j = 0; j < 32; ++j) {
            float e = expf(Ss[t][j] - mx);
            Ss[t][j] = e;
            sum += e;
        }
        float inv = 1.0f / sum;
#pragma unroll
        for (int j = 0; j < 32; ++j) Ss[t][j] *= inv;
    }
    __syncthreads();

    // Write attn [b,H,n,n]
    size_t abase = (size_t)bh * 1024;
#pragma unroll
    for (int r = 0; r < 8; ++r) {
        int p = t + 128 * r;
        attn_out[abase + p] = Ss[p >> 5][p & 31];
    }

    // ctx = P @ V, write to [b, n, h*64 + d]
    float* cbase = ctx + (size_t)b * Nn * HIDd + h * Dd;
#pragma unroll
    for (int r = 0; r < 16; ++r) {
        int o = t + 128 * r;             // 0..2047
        int i = o >> 6, d = o & 63;
        float acc = 0.0f;
#pragma unroll
        for (int j = 0; j < 32; ++j) acc += Ss[i][j] * Vs[j][d];
        cbase[(size_t)i * HIDd + d] = acc;
    }
}

// ---------------------------------------------------------------------------
// Launch
// ---------------------------------------------------------------------------
extern "C" void kernel_launch(void* const* d_in, const int* in_sizes, int n_in,
                              void* d_out, int out_size) {
    const float*         X    = (const float*)d_in[0];
    const unsigned char* mask = (const unsigned char*)d_in[1];
    const float*         Wqkv = (const float*)d_in[2];
    const float*         bqkv = (const float*)d_in[3];
    const float*         Wo   = (const float*)d_in[4];
    const float*         bo   = (const float*)d_in[5];

    float *qkv_p, *ctx_p, *attn_fb_p;
    cudaGetSymbolAddress((void**)&qkv_p, g_qkv);
    cudaGetSymbolAddress((void**)&ctx_p, g_ctx);
    cudaGetSymbolAddress((void**)&attn_fb_p, g_attn_fb);

    float* out = (float*)d_out;
    float* out_p;
    float* attn_p;
    long long osz = (long long)out_size;
    if (osz >= (long long)(OUT_ELEMS + ATTN_ELEMS)) {
        out_p  = out;
        attn_p = out + OUT_ELEMS;
    } else if (osz >= (long long)OUT_ELEMS) {
        out_p  = out;
        attn_p = attn_fb_p;
    } else {
        // d_out only fits attn (defensive)
        attn_p = out;
        out_p  = qkv_p;  // qkv scratch is dead after attention
    }

    decode_mask_kernel<<<1, 32>>>(mask);

    // qkv = X @ Wqkv^T + bqkv   [131072 x 1536]
    sgemm_nt_bias<<<dim3(MROWS / GBM, QKV_COLS / GBN), 256>>>(
        X, Wqkv, bqkv, qkv_p, MROWS, QKV_COLS, HIDd);

    // attention per (b,h)
    attn_kernel<<<Bsz * Hh, 128>>>(qkv_p, ctx_p, attn_p);

    // out = ctx @ Wo^T + bo     [131072 x 512]
    sgemm_nt_bias<<<dim3(MROWS / GBM, HIDd / GBN), 256>>>(
        ctx_p, Wo, bo, out_p, MROWS, HIDd, HIDd);
}

// round 6
// speedup vs baseline: 1.9668x; 1.9668x over previous
#include <cuda_runtime.h>
#include <cuda_bf16.h>
#include <math.h>
#include <stdint.h>

#define Bsz   4096
#define Nn    32
#define Hh    8
#define Dd    64
#define HIDd  512
#define MROWS (Bsz * Nn)
#define QKV_COLS (3 * HIDd)
#define Kdim  512

static const size_t OUT_ELEMS  = (size_t)MROWS * HIDd;
static const size_t ATTN_ELEMS = (size_t)Bsz * Hh * Nn * Nn;

__device__ float g_qkv[(size_t)MROWS * QKV_COLS];
__device__ float g_ctx[(size_t)MROWS * HIDd];
__device__ __nv_bfloat16 g_Ahi[(size_t)MROWS * HIDd];
__device__ __nv_bfloat16 g_Alo[(size_t)MROWS * HIDd];
__device__ __nv_bfloat16 g_Whi[1048576 + 16];
__device__ __nv_bfloat16 g_Wlo[1048576 + 16];
__device__ float g_attn_fb[(size_t)Bsz * Hh * Nn * Nn];
__device__ unsigned int g_mask_bits[32];

#define WQKV_ELE (QKV_COLS * HIDd)

// ---------------- PTX helpers (all non-accel: sm_80/75 era) ----------------
__device__ __forceinline__ uint32_t smem_u32(const void* p) {
    uint32_t a;
    asm("{ .reg .u64 t; cvta.to.shared.u64 t, %1; cvt.u32.u64 %0, t; }"
        : "=r"(a) : "l"(p));
    return a;
}
__device__ __forceinline__ void cp16(uint32_t dst, const void* src) {
    asm volatile("cp.async.cg.shared.global [%0], [%1], 16;"
                 :: "r"(dst), "l"(src) : "memory");
}
#define CP_COMMIT() asm volatile("cp.async.commit_group;" ::: "memory")
#define CP_WAIT1()  asm volatile("cp.async.wait_group 1;" ::: "memory")
#define CP_WAIT0()  asm volatile("cp.async.wait_group 0;" ::: "memory")

#define LDSM4(r0, r1, r2, r3, addr) \
    asm volatile("ldmatrix.sync.aligned.m8n8.x4.shared.b16 {%0,%1,%2,%3}, [%4];" \
        : "=r"(r0), "=r"(r1), "=r"(r2), "=r"(r3) : "r"(addr))

#define MMA16816(c, a, b0, b1) \
    asm volatile("mma.sync.aligned.m16n8k16.row.col.f32.bf16.bf16.f32 " \
        "{%0,%1,%2,%3}, {%4,%5,%6,%7}, {%8,%9}, {%0,%1,%2,%3};" \
        : "+f"((c)[0]), "+f"((c)[1]), "+f"((c)[2]), "+f"((c)[3]) \
        : "r"((a)[0]), "r"((a)[1]), "r"((a)[2]), "r"((a)[3]), \
          "r"(b0), "r"(b1))

// ---------------- mask decode ----------------
__global__ void decode_mask_kernel(const unsigned char* __restrict__ raw) {
    __shared__ int onebyte;
    if (threadIdx.x == 0) {
        int ok = 1;
        for (int i = 0; i < 32; ++i) if (raw[33 * i] == 0) ok = 0;
        onebyte = ok;
    }
    __syncthreads();
    int i = threadIdx.x;
    unsigned int bits = 0;
    if (onebyte) {
        for (int j = 0; j < 32; ++j)
            if (raw[i * 32 + j] != 0) bits |= (1u << j);
    } else {
        const unsigned int* w = (const unsigned int*)raw;
        for (int j = 0; j < 32; ++j)
            if (w[i * 32 + j] != 0) bits |= (1u << j);
    }
    g_mask_bits[i] = bits;
}

// ---------------- fp32 -> bf16 hi/lo split ----------------
__global__ void __launch_bounds__(256)
split_kernel(const float* __restrict__ in, __nv_bfloat16* __restrict__ hi,
             __nv_bfloat16* __restrict__ lo, int n4)
{
    int i = blockIdx.x * 256 + threadIdx.x;
    if (i >= n4) return;
    float4 x = ((const float4*)in)[i];
    __nv_bfloat16 h0 = __float2bfloat16(x.x), h1 = __float2bfloat16(x.y);
    __nv_bfloat16 h2 = __float2bfloat16(x.z), h3 = __float2bfloat16(x.w);
    __nv_bfloat16 l0 = __float2bfloat16(x.x - __bfloat162float(h0));
    __nv_bfloat16 l1 = __float2bfloat16(x.y - __bfloat162float(h1));
    __nv_bfloat16 l2 = __float2bfloat16(x.z - __bfloat162float(h2));
    __nv_bfloat16 l3 = __float2bfloat16(x.w - __bfloat162float(h3));
    __nv_bfloat162 a; a.x = h0; a.y = h1;
    __nv_bfloat162 b; b.x = h2; b.y = h3;
    __nv_bfloat162 c; c.x = l0; c.y = l1;
    __nv_bfloat162 d; d.x = l2; d.y = l3;
    ((__nv_bfloat162*)hi)[2 * i + 0] = a;
    ((__nv_bfloat162*)hi)[2 * i + 1] = b;
    ((__nv_bfloat162*)lo)[2 * i + 0] = c;
    ((__nv_bfloat162*)lo)[2 * i + 1] = d;
}

// ---------------- mma.sync bf16 GEMM (NT) ----------------
// C[m,n] = sum_k A[m,k]*B[n,k] + bias[n]; compensated bf16 split:
// ah*bh + ah*bl + al*bh. CTA 128x128, KC=32, 8 warps (warp tile 32x64).
#define GM  128
#define GN  128
#define GKC 32
#define NCHUNK (Kdim / GKC)       // 16
#define APITCH 80                 // bytes per smem row (32 bf16 + 16B pad)
#define MAT_BYTES (128 * APITCH)  // 10240
#define STAGE_BYTES (4 * MAT_BYTES)   // Ahi|Alo|Bhi|Blo = 40960
#define GEMM_SMEM (2 * STAGE_BYTES)   // 81920

__global__ void __launch_bounds__(256, 2)
gemm_tc(const __nv_bfloat16* __restrict__ Ahi, const __nv_bfloat16* __restrict__ Alo,
        const __nv_bfloat16* __restrict__ Bhi, const __nv_bfloat16* __restrict__ Blo,
        const float* __restrict__ bias, float* __restrict__ C, int Nc)
{
    extern __shared__ char smem[];
    const uint32_t sb = smem_u32(smem);
    const int t = threadIdx.x, wid = t >> 5, lane = t & 31;
    const int bm = blockIdx.y * GM, bn = blockIdx.x * GN;
    const int wm = (wid & 3) * 32;     // warp M offset
    const int wn = (wid >> 2) * 64;    // warp N offset

    float acc[2][8][4];
#pragma unroll
    for (int i = 0; i < 2; ++i)
#pragma unroll
        for (int j = 0; j < 8; ++j)
#pragma unroll
            for (int q = 0; q < 4; ++q) acc[i][j][q] = 0.0f;

    auto load_stage = [&](int st, int k0) {
        uint32_t base = sb + st * (uint32_t)STAGE_BYTES;
#pragma unroll
        for (int it = 0; it < 2; ++it) {
            int idx = t + 256 * it;        // 0..511
            int r = idx >> 2, seg = idx & 3;
            uint32_t doff = (uint32_t)(r * APITCH + seg * 16);
            size_t soA = (size_t)(bm + r) * Kdim + k0 + seg * 8;
            size_t soB = (size_t)(bn + r) * Kdim + k0 + seg * 8;
            cp16(base + doff,                 Ahi + soA);
            cp16(base + MAT_BYTES + doff,     Alo + soA);
            cp16(base + 2 * MAT_BYTES + doff, Bhi + soB);
            cp16(base + 3 * MAT_BYTES + doff, Blo + soB);
        }
        CP_COMMIT();
    };

    load_stage(0, 0);

    const uint32_t lrow  = lane & 15;          // row within 16-row ldmatrix tile
    const uint32_t lcolb = (lane >> 4) * 16;   // byte col offset (0 or 16)

    for (int c = 0; c < NCHUNK; ++c) {
        if (c + 1 < NCHUNK) {
            load_stage((c + 1) & 1, (c + 1) * GKC);
            CP_WAIT1();
        } else {
            CP_WAIT0();
        }
        __syncthreads();

        uint32_t base = sb + (uint32_t)(c & 1) * STAGE_BYTES;
#pragma unroll
        for (int s = 0; s < 2; ++s) {          // two k16 steps in KC=32
            uint32_t colb = s * 32 + lcolb;
            // A fragments (hi & lo), two m16 tiles
            uint32_t Ah[2][4], Al[2][4];
#pragma unroll
            for (int mi = 0; mi < 2; ++mi) {
                uint32_t ad = base + (wm + mi * 16 + lrow) * APITCH + colb;
                LDSM4(Ah[mi][0], Ah[mi][1], Ah[mi][2], Ah[mi][3], ad);
                LDSM4(Al[mi][0], Al[mi][1], Al[mi][2], Al[mi][3], ad + MAT_BYTES);
            }
#pragma unroll
            for (int ni = 0; ni < 4; ++ni) {   // four n16 tiles
                uint32_t bd = base + 2 * MAT_BYTES
                            + (wn + ni * 16 + lrow) * APITCH + colb;
                uint32_t h0, h1, h2, h3, l0, l1, l2, l3;
                LDSM4(h0, h1, h2, h3, bd);
                LDSM4(l0, l1, l2, l3, bd + MAT_BYTES);
                // atom n=2ni uses {r0,r2}; atom n=2ni+1 uses {r1,r3}
#pragma unroll
                for (int mi = 0; mi < 2; ++mi) {
                    MMA16816(acc[mi][2 * ni],     Ah[mi], h0, h2);
                    MMA16816(acc[mi][2 * ni],     Ah[mi], l0, l2);
                    MMA16816(acc[mi][2 * ni],     Al[mi], h0, h2);
                    MMA16816(acc[mi][2 * ni + 1], Ah[mi], h1, h3);
                    MMA16816(acc[mi][2 * ni + 1], Ah[mi], l1, l3);
                    MMA16816(acc[mi][2 * ni + 1], Al[mi], h1, h3);
                }
            }
        }
        __syncthreads();
    }

    // Epilogue: c0/c1 -> (row, col..col+1), c2/c3 -> row+8
    const int row0 = bm + wm + (lane >> 2);
    const int col0 = bn + wn + (lane & 3) * 2;
#pragma unroll
    for (int mi = 0; mi < 2; ++mi) {
#pragma unroll
        for (int nj = 0; nj < 8; ++nj) {
            int r = row0 + mi * 16;
            int cc = col0 + nj * 8;
            float b0 = __ldg(&bias[cc]), b1 = __ldg(&bias[cc + 1]);
            float* p0 = C + (size_t)r * Nc + cc;
            float* p1 = C + (size_t)(r + 8) * Nc + cc;
            p0[0] = acc[mi][nj][0] + b0;
            p0[1] = acc[mi][nj][1] + b1;
            p1[0] = acc[mi][nj][2] + b0;
            p1[1] = acc[mi][nj][3] + b1;
        }
    }
}

// ---------------- attention v2 ----------------
__global__ void __launch_bounds__(128)
attn_kernel2(const float* __restrict__ qkv, float* __restrict__ ctx,
             float* __restrict__ attn_out)
{
    __shared__ float Qs[32][64];
    __shared__ float Ks[32][65];
    __shared__ float Vs[32][64];
    __shared__ float Ps[32][33];

    const int bh = blockIdx.x;
    const int b  = bh >> 3;
    const int h  = bh & 7;
    const int t  = threadIdx.x;
    const int wid = t >> 5, lane = t & 31;

    const float* base = qkv + (size_t)b * Nn * QKV_COLS + h * Dd;
#pragma unroll
    for (int r = 0; r < 4; ++r) {
        int idx = t + 128 * r;
        int i = idx >> 4, d4 = (idx & 15) * 4;
        size_t ro = (size_t)i * QKV_COLS + d4;
        float4 q = *(const float4*)&base[ro];
        float4 k = *(const float4*)&base[ro + HIDd];
        float4 v = *(const float4*)&base[ro + 2 * HIDd];
        *(float4*)&Qs[i][d4] = q;
        Ks[i][d4 + 0] = k.x; Ks[i][d4 + 1] = k.y;
        Ks[i][d4 + 2] = k.z; Ks[i][d4 + 3] = k.w;
        *(float4*)&Vs[i][d4] = v;
    }
    __syncthreads();

    {   // scores: warp wid owns rows [8w,8w+8), lane = column j
        const int j = lane;
        float a8[8];
#pragma unroll
        for (int r = 0; r < 8; ++r) a8[r] = 0.0f;
#pragma unroll 4
        for (int d = 0; d < 64; ++d) {
            float kv = Ks[j][d];
#pragma unroll
            for (int r = 0; r < 8; ++r)
                a8[r] += Qs[wid * 8 + r][d] * kv;
        }
        size_t abase = (size_t)bh * 1024;
#pragma unroll
        for (int r = 0; r < 8; ++r) {
            int i = wid * 8 + r;
            float s = ((g_mask_bits[i] >> j) & 1u) ? a8[r] * 0.125f : -1e9f;
            float mx = s;
#pragma unroll
            for (int o = 16; o; o >>= 1)
                mx = fmaxf(mx, __shfl_xor_sync(0xFFFFFFFFu, mx, o));
            float e = expf(s - mx);
            float sum = e;
#pragma unroll
            for (int o = 16; o; o >>= 1)
                sum += __shfl_xor_sync(0xFFFFFFFFu, sum, o);
            float pr = e / sum;
            Ps[i][j] = pr;
            attn_out[abase + (size_t)i * 32 + j] = pr;
        }
    }
    __syncthreads();

    {   // PV: thread -> (half hh, column d)
        const int d  = t & 63;
        const int hh = t >> 6;
        float a2[16];
#pragma unroll
        for (int r = 0; r < 16; ++r) a2[r] = 0.0f;
#pragma unroll 4
        for (int j = 0; j < 32; ++j) {
            float v = Vs[j][d];
#pragma unroll
            for (int r = 0; r < 16; ++r)
                a2[r] += Ps[hh * 16 + r][j] * v;
        }
        float* cbase = ctx + (size_t)b * Nn * HIDd + h * Dd;
#pragma unroll
        for (int r = 0; r < 16; ++r)
            cbase[(size_t)(hh * 16 + r) * HIDd + d] = a2[r];
    }
}

// ---------------- launch ----------------
extern "C" void kernel_launch(void* const* d_in, const int* in_sizes, int n_in,
                              void* d_out, int out_size) {
    const float*         X    = (const float*)d_in[0];
    const unsigned char* mask = (const unsigned char*)d_in[1];
    const float*         Wqkv = (const float*)d_in[2];
    const float*         bqkv = (const float*)d_in[3];
    const float*         Wo   = (const float*)d_in[4];
    const float*         bo   = (const float*)d_in[5];

    float *qkv_p, *ctx_p, *attn_fb_p;
    __nv_bfloat16 *ahi_p, *alo_p, *whi_p, *wlo_p;
    cudaGetSymbolAddress((void**)&qkv_p, g_qkv);
    cudaGetSymbolAddress((void**)&ctx_p, g_ctx);
    cudaGetSymbolAddress((void**)&attn_fb_p, g_attn_fb);
    cudaGetSymbolAddress((void**)&ahi_p, g_Ahi);
    cudaGetSymbolAddress((void**)&alo_p, g_Alo);
    cudaGetSymbolAddress((void**)&whi_p, g_Whi);
    cudaGetSymbolAddress((void**)&wlo_p, g_Wlo);

    float* out = (float*)d_out;
    float *out_p, *attn_p;
    long long osz = (long long)out_size;
    if (osz >= (long long)(OUT_ELEMS + ATTN_ELEMS)) {
        out_p = out; attn_p = out + OUT_ELEMS;
    } else if (osz >= (long long)OUT_ELEMS) {
        out_p = out; attn_p = attn_fb_p;
    } else {
        attn_p = out; out_p = qkv_p;
    }

    cudaFuncSetAttribute(gemm_tc, cudaFuncAttributeMaxDynamicSharedMemorySize,
                         GEMM_SMEM);

    decode_mask_kernel<<<1, 32>>>(mask);

    // splits: X, Wqkv, Wo
    {
        int n4 = (MROWS * HIDd) / 4;
        split_kernel<<<(n4 + 255) / 256, 256>>>(X, ahi_p, alo_p, n4);
        int w4 = WQKV_ELE / 4;
        split_kernel<<<(w4 + 255) / 256, 256>>>(Wqkv, whi_p, wlo_p, w4);
        int o4 = (HIDd * HIDd) / 4;
        split_kernel<<<(o4 + 255) / 256, 256>>>(Wo, whi_p + WQKV_ELE,
                                                wlo_p + WQKV_ELE, o4);
    }

    // qkv = X @ Wqkv^T + bqkv   [131072 x 1536]
    gemm_tc<<<dim3(QKV_COLS / GN, MROWS / GM), 256, GEMM_SMEM>>>(
        ahi_p, alo_p, whi_p, wlo_p, bqkv, qkv_p, QKV_COLS);

    // attention
    attn_kernel2<<<Bsz * Hh, 128>>>(qkv_p, ctx_p, attn_p);

    // split ctx (reuse Ahi/Alo)
    {
        int n4 = (MROWS * HIDd) / 4;
        split_kernel<<<(n4 + 255) / 256, 256>>>(ctx_p, ahi_p, alo_p, n4);
    }

    // out = ctx @ Wo^T + bo     [131072 x 512]
    gemm_tc<<<dim3(HIDd / GN, MROWS / GM), 256, GEMM_SMEM>>>(
        ahi_p, alo_p, whi_p + WQKV_ELE, wlo_p + WQKV_ELE, bo, out_p, HIDd);
}